// round 3
// baseline (speedup 1.0000x reference)
#include <cuda_runtime.h>
#include <cuda_bf16.h>
#include <cstdint>

#define B_ 64
#define S_ 512
#define D_ 512
#define NCHUNK 16   // 512 / 32
#define SROW 40     // smem row stride in bf16 (32 data + 8 pad), conflict-free ldmatrix

// ---- scratch (static device allocations; no cudaMalloc allowed) ----
__device__ unsigned g_rowmax[B_ * S_];
__device__ unsigned g_colmax[B_ * S_];
__device__ int g_n1[B_];
__device__ int g_n2[B_];
__device__ int g_total[B_];
__device__ int g_cnt[B_];

// order-preserving float<->uint transform so atomicMax(unsigned) == float max
__device__ __forceinline__ unsigned enc_f(float f) {
    unsigned u = __float_as_uint(f);
    return (u & 0x80000000u) ? ~u : (u | 0x80000000u);
}
__device__ __forceinline__ float dec_f(unsigned u) {
    return (u & 0x80000000u) ? __uint_as_float(u ^ 0x80000000u) : __uint_as_float(~u);
}

// ---- kernel 1: mask sums + init buffers ----
__global__ void prep_kernel(const int* __restrict__ m1, const int* __restrict__ m2) {
    int b = blockIdx.x, t = threadIdx.x;
    int s1 = 0, s2 = 0;
    for (int i = t; i < S_; i += 256) {
        s1 += m1[b * S_ + i];
        s2 += m2[b * S_ + i];
        g_rowmax[b * S_ + i] = 0u;   // enc-min
        g_colmax[b * S_ + i] = 0u;
    }
#pragma unroll
    for (int o = 16; o; o >>= 1) {
        s1 += __shfl_xor_sync(0xffffffffu, s1, o);
        s2 += __shfl_xor_sync(0xffffffffu, s2, o);
    }
    __shared__ int r1[8], r2[8];
    if ((t & 31) == 0) { r1[t >> 5] = s1; r2[t >> 5] = s2; }
    __syncthreads();
    if (t == 0) {
        int a = 0, c = 0;
#pragma unroll
        for (int w = 0; w < 8; w++) { a += r1[w]; c += r2[w]; }
        g_n1[b] = a;
        g_n2[b] = c;
        g_total[b] = ((a + 127) >> 7) * ((c + 127) >> 7);
        g_cnt[b] = 0;
    }
}

// ---- kernel 2: fully fused — load f32, on-the-fly bf16 convert + sum-of-squares,
//      128x128 mma.sync Gram tile, post-scale by inv-norms, masked row/col max,
//      last-tile-per-batch does the final reduction and writes out[b]. ----
__global__ void __launch_bounds__(256) sim_kernel(const float* __restrict__ E1,
                                                  const float* __restrict__ E2,
                                                  float* __restrict__ out) {
    int b = blockIdx.z;
    int n1 = g_n1[b], n2 = g_n2[b];
    int i0 = blockIdx.y * 128, j0 = blockIdx.x * 128;
    if (i0 >= n1 || j0 >= n2) return;   // prefix-mask tile skipping

    __shared__ __align__(16) __nv_bfloat16 As[128 * SROW];
    __shared__ __align__(16) __nv_bfloat16 Bs[128 * SROW];
    __shared__ float invA[128], invB[128];
    __shared__ int isLast;

    int tid = threadIdx.x, lane = tid & 31, warp = tid >> 5;
    int wm = warp >> 2, wn = warp & 3;   // 2 x 4 warp grid, warp tile 64x32

    // conversion-loader mapping: 2 threads per row, 16 f32 each per 32-chunk
    int lrow = tid >> 1;
    int hv = tid & 1;

    const float* Ag = E1 + ((size_t)b * S_ + i0 + lrow) * D_ + hv * 16;
    const float* Bg = E2 + ((size_t)b * S_ + j0 + lrow) * D_ + hv * 16;

    float acc[4][4][4];
#pragma unroll
    for (int a = 0; a < 4; a++)
#pragma unroll
        for (int c = 0; c < 4; c++)
#pragma unroll
            for (int d = 0; d < 4; d++) acc[a][c][d] = 0.f;

    float4 va[4], vb[4];
    float ss_a = 0.f, ss_b = 0.f;

#pragma unroll
    for (int q = 0; q < 4; q++) {
        va[q] = *(const float4*)(Ag + q * 4);
        vb[q] = *(const float4*)(Bg + q * 4);
    }

#pragma unroll 1
    for (int kc = 0; kc < NCHUNK; kc++) {
        // convert current regs -> bf16 smem, accumulate sum-of-squares
#pragma unroll
        for (int q = 0; q < 4; q++) {
            float4 a4 = va[q], b4 = vb[q];
            ss_a += a4.x * a4.x + a4.y * a4.y + a4.z * a4.z + a4.w * a4.w;
            ss_b += b4.x * b4.x + b4.y * b4.y + b4.z * b4.z + b4.w * b4.w;
            __nv_bfloat162 p0 = __floats2bfloat162_rn(a4.x, a4.y);
            __nv_bfloat162 p1 = __floats2bfloat162_rn(a4.z, a4.w);
            uint2 ua;
            ua.x = *(unsigned*)&p0; ua.y = *(unsigned*)&p1;
            *(uint2*)&As[lrow * SROW + hv * 16 + q * 4] = ua;
            __nv_bfloat162 q0 = __floats2bfloat162_rn(b4.x, b4.y);
            __nv_bfloat162 q1 = __floats2bfloat162_rn(b4.z, b4.w);
            uint2 ub;
            ub.x = *(unsigned*)&q0; ub.y = *(unsigned*)&q1;
            *(uint2*)&Bs[lrow * SROW + hv * 16 + q * 4] = ub;
        }
        __syncthreads();

        // prefetch next chunk while tensor pipe works on this one
        if (kc + 1 < NCHUNK) {
            const float* an = Ag + (kc + 1) * 32;
            const float* bn = Bg + (kc + 1) * 32;
#pragma unroll
            for (int q = 0; q < 4; q++) {
                va[q] = *(const float4*)(an + q * 4);
                vb[q] = *(const float4*)(bn + q * 4);
            }
        }

#pragma unroll
        for (int ks = 0; ks < 2; ks++) {
            uint32_t af[4][4];
#pragma unroll
            for (int tm = 0; tm < 4; tm++) {
                int row = wm * 64 + tm * 16 + (lane & 15);
                int col = ks * 16 + (lane >> 4) * 8;
                uint32_t addr = (uint32_t)__cvta_generic_to_shared(&As[row * SROW + col]);
                asm volatile("ldmatrix.sync.aligned.m8n8.x4.shared.b16 {%0,%1,%2,%3},[%4];\n"
                             : "=r"(af[tm][0]), "=r"(af[tm][1]), "=r"(af[tm][2]), "=r"(af[tm][3])
                             : "r"(addr));
            }
            uint32_t bfr[4][2];
#pragma unroll
            for (int tn = 0; tn < 4; tn++) {
                int l = lane & 15;
                int rowb = wn * 32 + tn * 8 + (l & 7);
                int colb = ks * 16 + (l >> 3) * 8;
                uint32_t addr = (uint32_t)__cvta_generic_to_shared(&Bs[rowb * SROW + colb]);
                asm volatile("ldmatrix.sync.aligned.m8n8.x2.shared.b16 {%0,%1},[%2];\n"
                             : "=r"(bfr[tn][0]), "=r"(bfr[tn][1])
                             : "r"(addr));
            }
#pragma unroll
            for (int tm = 0; tm < 4; tm++)
#pragma unroll
                for (int tn = 0; tn < 4; tn++)
                    asm volatile(
                        "mma.sync.aligned.m16n8k16.row.col.f32.bf16.bf16.f32 "
                        "{%0,%1,%2,%3},{%4,%5,%6,%7},{%8,%9},{%0,%1,%2,%3};\n"
                        : "+f"(acc[tm][tn][0]), "+f"(acc[tm][tn][1]),
                          "+f"(acc[tm][tn][2]), "+f"(acc[tm][tn][3])
                        : "r"(af[tm][0]), "r"(af[tm][1]), "r"(af[tm][2]), "r"(af[tm][3]),
                          "r"(bfr[tn][0]), "r"(bfr[tn][1]));
        }
        __syncthreads();
    }

    // ---- inverse norms (reference: x / max(sqrt(ss), 1e-8)) ----
    {
        float sa = ss_a + __shfl_xor_sync(0xffffffffu, ss_a, 1);
        float sb = ss_b + __shfl_xor_sync(0xffffffffu, ss_b, 1);
        if (hv == 0) {
            invA[lrow] = 1.0f / fmaxf(sqrtf(sa), 1e-8f);
            invB[lrow] = 1.0f / fmaxf(sqrtf(sb), 1e-8f);
        }
    }
    __syncthreads();

    // ---- fused masked reductions (scale by inv norms; positive => max-safe) ----
    const float NEGINF = -3.0e38f;

    // row max over valid j
#pragma unroll
    for (int tm = 0; tm < 4; tm++) {
#pragma unroll
        for (int rr = 0; rr < 2; rr++) {
            float v = NEGINF;
#pragma unroll
            for (int tn = 0; tn < 4; tn++) {
#pragma unroll
                for (int cc = 0; cc < 2; cc++) {
                    int jl = wn * 32 + tn * 8 + (lane & 3) * 2 + cc;
                    if (j0 + jl < n2) v = fmaxf(v, acc[tm][tn][rr * 2 + cc] * invB[jl]);
                }
            }
            v = fmaxf(v, __shfl_xor_sync(0xffffffffu, v, 1));
            v = fmaxf(v, __shfl_xor_sync(0xffffffffu, v, 2));
            if ((lane & 3) == 0) {
                int il = wm * 64 + tm * 16 + (lane >> 2) + rr * 8;
                if (i0 + il < n1) atomicMax(&g_rowmax[b * S_ + i0 + il], enc_f(v * invA[il]));
            }
        }
    }

    // col max over valid i
#pragma unroll
    for (int tn = 0; tn < 4; tn++) {
#pragma unroll
        for (int cc = 0; cc < 2; cc++) {
            float v = NEGINF;
#pragma unroll
            for (int tm = 0; tm < 4; tm++) {
#pragma unroll
                for (int rr = 0; rr < 2; rr++) {
                    int il = wm * 64 + tm * 16 + (lane >> 2) + rr * 8;
                    if (i0 + il < n1) v = fmaxf(v, acc[tm][tn][rr * 2 + cc] * invA[il]);
                }
            }
            v = fmaxf(v, __shfl_xor_sync(0xffffffffu, v, 4));
            v = fmaxf(v, __shfl_xor_sync(0xffffffffu, v, 8));
            v = fmaxf(v, __shfl_xor_sync(0xffffffffu, v, 16));
            if (lane < 4) {
                int jl = wn * 32 + tn * 8 + lane * 2 + cc;
                if (j0 + jl < n2) atomicMax(&g_colmax[b * S_ + j0 + jl], enc_f(v * invB[jl]));
            }
        }
    }

    // ---- last tile of this batch performs the final reduction ----
    __threadfence();
    __syncthreads();
    if (tid == 0) {
        int c = atomicAdd(&g_cnt[b], 1);
        isLast = (c == g_total[b] - 1);
    }
    __syncthreads();
    if (!isLast) return;

    float s = 0.f;
    for (int i = tid; i < n1; i += 256) s += dec_f(__ldcg(&g_rowmax[b * S_ + i]));
    for (int j = tid; j < n2; j += 256) s += dec_f(__ldcg(&g_colmax[b * S_ + j]));
#pragma unroll
    for (int o = 16; o; o >>= 1) s += __shfl_xor_sync(0xffffffffu, s, o);
    __shared__ float red[8];
    if ((tid & 31) == 0) red[tid >> 5] = s;
    __syncthreads();
    if (tid == 0) {
        float tot = 0.f;
#pragma unroll
        for (int w = 0; w < 8; w++) tot += red[w];
        out[b] = tot / (float)(n1 + n2);
    }
}

extern "C" void kernel_launch(void* const* d_in, const int* in_sizes, int n_in,
                              void* d_out, int out_size) {
    (void)in_sizes; (void)n_in; (void)out_size;
    const float* e1 = (const float*)d_in[0];
    const float* e2 = (const float*)d_in[1];
    const int* m1 = (const int*)d_in[2];
    const int* m2 = (const int*)d_in[3];

    prep_kernel<<<B_, 256>>>(m1, m2);
    sim_kernel<<<dim3(4, 4, B_), 256>>>(e1, e2, (float*)d_out);
}